// round 7
// baseline (speedup 1.0000x reference)
#include <cuda_runtime.h>
#include <cstdint>

#define N_B 8
#define T_S 1024
#define D_IN 512
#define U_D 512
#define H_N 8
#define D_H 64

// Scratch for projected Q, K, V: [N, T, U] fp32 (tf32-rounded; Q pre-scaled).
__device__ float g_Q[N_B * T_S * U_D];
__device__ float g_K[N_B * T_S * U_D];
__device__ float g_V[N_B * T_S * U_D];

// ---------------------------------------------------------------------------
// Helpers
// ---------------------------------------------------------------------------
__device__ __forceinline__ uint32_t f2tf32(float x) {
    uint32_t r;
    asm("cvt.rna.tf32.f32 %0, %1;" : "=r"(r) : "f"(x));
    return r;
}
__device__ __forceinline__ float f2tf32f(float x) { return __uint_as_float(f2tf32(x)); }

// D += A*B, m16n8k8 tf32. a[4], b[2] are tf32 bit patterns.
__device__ __forceinline__ void mma_tf32(float* d, const uint32_t* a, const uint32_t* b) {
    asm volatile(
        "mma.sync.aligned.m16n8k8.row.col.f32.tf32.tf32.f32 "
        "{%0,%1,%2,%3},{%4,%5,%6,%7},{%8,%9},{%0,%1,%2,%3};\n"
        : "+f"(d[0]), "+f"(d[1]), "+f"(d[2]), "+f"(d[3])
        : "r"(a[0]), "r"(a[1]), "r"(a[2]), "r"(a[3]), "r"(b[0]), "r"(b[1]));
}

__device__ __forceinline__ void ldsm4(uint32_t& r0, uint32_t& r1, uint32_t& r2, uint32_t& r3,
                                      uint32_t addr) {
    asm volatile("ldmatrix.sync.aligned.m8n8.x4.shared.b16 {%0,%1,%2,%3}, [%4];"
                 : "=r"(r0), "=r"(r1), "=r"(r2), "=r"(r3)
                 : "r"(addr));
}

__device__ __forceinline__ void cp_async16(float* s, const float* g) {
    uint32_t sa = (uint32_t)__cvta_generic_to_shared(s);
    asm volatile("cp.async.cg.shared.global [%0], [%1], 16;\n" :: "r"(sa), "l"(g));
}
__device__ __forceinline__ void cp_commit() { asm volatile("cp.async.commit_group;\n"); }
template <int N>
__device__ __forceinline__ void cp_wait() { asm volatile("cp.async.wait_group %0;\n" :: "n"(N)); }

// ---------------------------------------------------------------------------
// Projection GEMM: C[8192,512] = X[8192,512] @ W[512,512]
// Register-prefetch pipeline, cvt-at-STS, single smem buffer, B_LD=72.
// Epilogue rounds output to tf32 (Q additionally folded with 1/sqrt(512)) so
// the attention kernel can consume gmem directly without conversions.
// ---------------------------------------------------------------------------
#define GBM 128
#define GBN 64
#define GBK 32
#define A_LD 36
#define B_LD 72
#define SM_GEMM ((GBM * A_LD + GBK * B_LD) * 4)

__global__ void __launch_bounds__(256) proj_gemm(
    const float* __restrict__ Xq, const float* __restrict__ Xk,
    const float* __restrict__ Wq, const float* __restrict__ Wk,
    const float* __restrict__ Wv) {
    const float* X;
    const float* W;
    float* C;
    float oscale;
    if (blockIdx.z == 0) { X = Xq; W = Wq; C = g_Q; oscale = 0.04419417382415922f; }
    else if (blockIdx.z == 1) { X = Xk; W = Wk; C = g_K; oscale = 1.0f; }
    else { X = Xk; W = Wv; C = g_V; oscale = 1.0f; }

    extern __shared__ float sm[];
    float* As = sm;                 // [GBM][A_LD]
    float* Bs = sm + GBM * A_LD;    // [GBK][B_LD]

    const int tid = threadIdx.x;
    const int m0 = blockIdx.x * GBM, n0 = blockIdx.y * GBN;
    const int ar = tid >> 3, ac = (tid & 7) * 4;
    const int br = tid >> 4, bc = (tid & 15) * 4;

    const int lane = tid & 31, wid = tid >> 5;
    const int g = lane >> 2, tg = lane & 3;
    const int wm = (wid & 3) * 32, wn = (wid >> 2) * 32;

    float acc[2][4][4];
#pragma unroll
    for (int mf = 0; mf < 2; mf++)
#pragma unroll
        for (int nf = 0; nf < 4; nf++)
#pragma unroll
            for (int i = 0; i < 4; i++) acc[mf][nf][i] = 0.f;

    const int NK = D_IN / GBK;  // 16

    float4 pa[4], pb[2];
    auto ldreg = [&](int kt) {
#pragma unroll
        for (int i = 0; i < 4; i++)
            pa[i] = *(const float4*)(X + (size_t)(m0 + ar + i * 32) * D_IN + kt * GBK + ac);
#pragma unroll
        for (int i = 0; i < 2; i++)
            pb[i] = *(const float4*)(W + (size_t)(kt * GBK + br + i * 16) * U_D + n0 + bc);
    };

    ldreg(0);

    for (int kt = 0; kt < NK; ++kt) {
        __syncthreads();
#pragma unroll
        for (int i = 0; i < 4; i++) {
            float4 o;
            o.x = f2tf32f(pa[i].x); o.y = f2tf32f(pa[i].y);
            o.z = f2tf32f(pa[i].z); o.w = f2tf32f(pa[i].w);
            *(float4*)(As + (ar + i * 32) * A_LD + ac) = o;
        }
#pragma unroll
        for (int i = 0; i < 2; i++) {
            float4 o;
            o.x = f2tf32f(pb[i].x); o.y = f2tf32f(pb[i].y);
            o.z = f2tf32f(pb[i].z); o.w = f2tf32f(pb[i].w);
            *(float4*)(Bs + (br + i * 16) * B_LD + bc) = o;
        }
        __syncthreads();

        if (kt + 1 < NK) ldreg(kt + 1);

#pragma unroll
        for (int kk = 0; kk < 4; kk++) {
            uint32_t a[2][4];
#pragma unroll
            for (int mf = 0; mf < 2; mf++) {
                const int rb = wm + mf * 16;
                a[mf][0] = __float_as_uint(As[(rb + g) * A_LD + kk * 8 + tg]);
                a[mf][1] = __float_as_uint(As[(rb + g + 8) * A_LD + kk * 8 + tg]);
                a[mf][2] = __float_as_uint(As[(rb + g) * A_LD + kk * 8 + tg + 4]);
                a[mf][3] = __float_as_uint(As[(rb + g + 8) * A_LD + kk * 8 + tg + 4]);
            }
            uint32_t b[4][2];
#pragma unroll
            for (int nf = 0; nf < 4; nf++) {
                b[nf][0] = __float_as_uint(Bs[(kk * 8 + tg) * B_LD + wn + nf * 8 + g]);
                b[nf][1] = __float_as_uint(Bs[(kk * 8 + tg + 4) * B_LD + wn + nf * 8 + g]);
            }
#pragma unroll
            for (int mf = 0; mf < 2; mf++)
#pragma unroll
                for (int nf = 0; nf < 4; nf++) mma_tf32(acc[mf][nf], a[mf], b[nf]);
        }
    }

    // epilogue: tf32-round (fold scale for Q) so attn consumes gmem directly
#pragma unroll
    for (int mf = 0; mf < 2; mf++) {
        const int r0 = m0 + wm + mf * 16 + g;
#pragma unroll
        for (int nf = 0; nf < 4; nf++) {
            const int c = n0 + wn + nf * 8 + 2 * tg;
            *(float2*)(C + (size_t)r0 * U_D + c) =
                make_float2(f2tf32f(acc[mf][nf][0] * oscale), f2tf32f(acc[mf][nf][1] * oscale));
            *(float2*)(C + (size_t)(r0 + 8) * U_D + c) =
                make_float2(f2tf32f(acc[mf][nf][2] * oscale), f2tf32f(acc[mf][nf][3] * oscale));
        }
    }
}

// ---------------------------------------------------------------------------
// Flash attention v5: KT=64 single-buffered K and V staged via cp.async with
// staggered pipelining (K(t+1) load overlaps softmax+PV(t); V(t+1) overlaps
// QK^T(t+1)). Gmem is pre-rounded tf32 (Q pre-scaled) -> no cvt in mainloop.
// CTA = 128 q-rows x 4 warps; warp owns 32 rows (2 m-frags).
// ---------------------------------------------------------------------------
#define QT 128
#define KT 64
#define AL 68     // LD for Qs/Ks/Ps
#define VL 72     // LD for Vs (8*tg+g hits all 32 banks)
#define SM_ATTN ((QT * AL + KT * AL + KT * VL + QT * AL + KT) * 4)

__global__ void __launch_bounds__(128) attn_kernel(const int* __restrict__ mask,
                                                   float* __restrict__ out) {
    extern __shared__ float sm[];
    float* Qs = sm;                       // [128][AL] tf32, scale folded
    float* Ks = Qs + QT * AL;             // [64][AL]  tf32
    float* Vs = Ks + KT * AL;             // [64][VL]  tf32
    float* Ps = Vs + KT * VL;             // [128][AL] tf32
    float* Msk = Ps + QT * AL;            // [64] 1.0 = masked-out

    const int tid = threadIdx.x, lane = tid & 31, wid = tid >> 5;
    const int g = lane >> 2, tg = lane & 3;
    const int q0 = blockIdx.x * QT;
    const int h = blockIdx.y, n = blockIdx.z;
    const int wrow = wid * 32;

    const uint32_t sQ = (uint32_t)__cvta_generic_to_shared(Qs);
    const uint32_t sK = (uint32_t)__cvta_generic_to_shared(Ks);
    const uint32_t sP = (uint32_t)__cvta_generic_to_shared(Ps);

    // ldmatrix per-lane offsets (floats)
    const int li = lane & 7, lj = lane >> 3;
    const int aoff = (li + (lj & 1) * 8) * AL + (lj >> 1) * 4;  // 16x8 A-frag
    const int boff = (li + (lj >> 1) * 8) * AL + (lj & 1) * 4;  // 2x(8k x 8c) B

    const int lr = tid >> 4;   // 0..7
    const int fc = tid & 15;   // float4 column

    // ---- Q prologue: straight copy (already tf32-rounded + scaled) ----
#pragma unroll
    for (int i = 0; i < 16; i++) {
        const int r = lr + i * 8;
        *(float4*)(Qs + r * AL + fc * 4) =
            *(const float4*)(g_Q + (size_t)(n * T_S + q0 + r) * U_D + h * D_H + fc * 4);
    }

    // cp.async staging: thread -> (row = tid>>1, half = tid&1), 8x16B each.
    const int crow = tid >> 1;
    const int chalf = (tid & 1) * 32;  // float offset of 8-chunk half
    auto issueK = [&](int t) {
        const float* gk = g_K + (size_t)(n * T_S + t * KT + crow) * U_D + h * D_H + chalf;
        float* dk = Ks + crow * AL + chalf;
#pragma unroll
        for (int i = 0; i < 8; i++) cp_async16(dk + i * 4, gk + i * 4);
    };
    auto issueV = [&](int t) {
        const float* gv = g_V + (size_t)(n * T_S + t * KT + crow) * U_D + h * D_H + chalf;
        float* dv = Vs + crow * VL + chalf;
#pragma unroll
        for (int i = 0; i < 8; i++) cp_async16(dv + i * 4, gv + i * 4);
    };

    float mr[2][2], lsum[2][2];
#pragma unroll
    for (int mf = 0; mf < 2; mf++) { mr[mf][0] = mr[mf][1] = -1e30f; lsum[mf][0] = lsum[mf][1] = 0.f; }
    float of[2][8][4];
#pragma unroll
    for (int mf = 0; mf < 2; mf++)
#pragma unroll
        for (int nf = 0; nf < 8; nf++)
#pragma unroll
            for (int i = 0; i < 4; i++) of[mf][nf][i] = 0.f;

    // prologue: stage tile 0 (K group, then V group)
    issueK(0);
    cp_commit();
    issueV(0);
    cp_commit();

    const int NT = T_S / KT;  // 16
    for (int t = 0; t < NT; t++) {
        // K(t) ready (newest group V(t) may still be in flight)
        cp_wait<1>();
        __syncthreads();  // S1: Ks(t) visible; prior-iter consumers done

        if (tid < KT) Msk[tid] = (mask[n * T_S + t * KT + tid] != 0) ? 0.f : 1.f;

        // ---- S = Q @ K^T ----
        float sf[2][8][4];
#pragma unroll
        for (int mf = 0; mf < 2; mf++)
#pragma unroll
            for (int nf = 0; nf < 8; nf++)
#pragma unroll
                for (int i = 0; i < 4; i++) sf[mf][nf][i] = 0.f;

#pragma unroll
        for (int kk = 0; kk < 8; kk++) {
            uint32_t qa[2][4];
            ldsm4(qa[0][0], qa[0][1], qa[0][2], qa[0][3],
                  sQ + 4u * (uint32_t)(wrow * AL + kk * 8 + aoff));
            ldsm4(qa[1][0], qa[1][1], qa[1][2], qa[1][3],
                  sQ + 4u * (uint32_t)((wrow + 16) * AL + kk * 8 + aoff));
#pragma unroll
            for (int nfp = 0; nfp < 4; nfp++) {
                uint32_t kb[4];
                ldsm4(kb[0], kb[1], kb[2], kb[3],
                      sK + 4u * (uint32_t)(nfp * 16 * AL + kk * 8 + boff));
                mma_tf32(sf[0][2 * nfp], qa[0], kb);
                mma_tf32(sf[1][2 * nfp], qa[1], kb);
                mma_tf32(sf[0][2 * nfp + 1], qa[0], kb + 2);
                mma_tf32(sf[1][2 * nfp + 1], qa[1], kb + 2);
            }
        }
        __syncthreads();  // S2: all warps done reading Ks; Msk visible

        // overlap K(t+1) with softmax + PV (always commit to keep counts uniform)
        if (t + 1 < NT) issueK(t + 1);
        cp_commit();

        // ---- mask (jnp.where(mask, s, -1e6)) ----
#pragma unroll
        for (int nf = 0; nf < 8; nf++) {
            const float f0 = Msk[nf * 8 + 2 * tg];
            const float f1 = Msk[nf * 8 + 2 * tg + 1];
#pragma unroll
            for (int mf = 0; mf < 2; mf++) {
                if (f0 != 0.f) { sf[mf][nf][0] = -1e6f; sf[mf][nf][2] = -1e6f; }
                if (f1 != 0.f) { sf[mf][nf][1] = -1e6f; sf[mf][nf][3] = -1e6f; }
            }
        }

        // ---- online softmax + P store ----
#pragma unroll
        for (int mf = 0; mf < 2; mf++) {
            float rm0 = -1e30f, rm1 = -1e30f;
#pragma unroll
            for (int nf = 0; nf < 8; nf++) {
                rm0 = fmaxf(rm0, fmaxf(sf[mf][nf][0], sf[mf][nf][1]));
                rm1 = fmaxf(rm1, fmaxf(sf[mf][nf][2], sf[mf][nf][3]));
            }
            rm0 = fmaxf(rm0, __shfl_xor_sync(0xffffffffu, rm0, 1));
            rm0 = fmaxf(rm0, __shfl_xor_sync(0xffffffffu, rm0, 2));
            rm1 = fmaxf(rm1, __shfl_xor_sync(0xffffffffu, rm1, 1));
            rm1 = fmaxf(rm1, __shfl_xor_sync(0xffffffffu, rm1, 2));

            const float mn0 = fmaxf(mr[mf][0], rm0), mn1 = fmaxf(mr[mf][1], rm1);
            const float al0 = __expf(mr[mf][0] - mn0), al1 = __expf(mr[mf][1] - mn1);
            float rs0 = 0.f, rs1 = 0.f;
#pragma unroll
            for (int nf = 0; nf < 8; nf++) {
                sf[mf][nf][0] = __expf(sf[mf][nf][0] - mn0);
                sf[mf][nf][1] = __expf(sf[mf][nf][1] - mn0);
                sf[mf][nf][2] = __expf(sf[mf][nf][2] - mn1);
                sf[mf][nf][3] = __expf(sf[mf][nf][3] - mn1);
                rs0 += sf[mf][nf][0] + sf[mf][nf][1];
                rs1 += sf[mf][nf][2] + sf[mf][nf][3];
            }
            rs0 += __shfl_xor_sync(0xffffffffu, rs0, 1);
            rs0 += __shfl_xor_sync(0xffffffffu, rs0, 2);
            rs1 += __shfl_xor_sync(0xffffffffu, rs1, 1);
            rs1 += __shfl_xor_sync(0xffffffffu, rs1, 2);

            lsum[mf][0] = lsum[mf][0] * al0 + rs0;
            lsum[mf][1] = lsum[mf][1] * al1 + rs1;
            mr[mf][0] = mn0;
            mr[mf][1] = mn1;

#pragma unroll
            for (int nf = 0; nf < 8; nf++) {
                of[mf][nf][0] *= al0;
                of[mf][nf][1] *= al0;
                of[mf][nf][2] *= al1;
                of[mf][nf][3] *= al1;
            }

            const int pr = wrow + mf * 16;
#pragma unroll
            for (int nf = 0; nf < 8; nf++) {
                *(float2*)(Ps + (pr + g) * AL + nf * 8 + 2 * tg) =
                    make_float2(f2tf32f(sf[mf][nf][0]), f2tf32f(sf[mf][nf][1]));
                *(float2*)(Ps + (pr + g + 8) * AL + nf * 8 + 2 * tg) =
                    make_float2(f2tf32f(sf[mf][nf][2]), f2tf32f(sf[mf][nf][3]));
            }
        }
        __syncwarp();

        // V(t) ready (newest group K(t+1) may still be in flight)
        cp_wait<1>();
        __syncthreads();  // S3: Vs(t) visible to all warps

        // ---- O += P @ V ----
#pragma unroll
        for (int kks = 0; kks < 8; kks++) {
            uint32_t pa[2][4];
            ldsm4(pa[0][0], pa[0][1], pa[0][2], pa[0][3],
                  sP + 4u * (uint32_t)(wrow * AL + kks * 8 + aoff));
            ldsm4(pa[1][0], pa[1][1], pa[1][2], pa[1][3],
                  sP + 4u * (uint32_t)((wrow + 16) * AL + kks * 8 + aoff));
#pragma unroll
            for (int nf = 0; nf < 8; nf++) {
                uint32_t vb[2];
                vb[0] = __float_as_uint(Vs[(kks * 8 + tg) * VL + nf * 8 + g]);
                vb[1] = __float_as_uint(Vs[(kks * 8 + tg + 4) * VL + nf * 8 + g]);
                mma_tf32(of[0][nf], pa[0], vb);
                mma_tf32(of[1][nf], pa[1], vb);
            }
        }
        __syncthreads();  // S4: all warps done reading Vs

        if (t + 1 < NT) {
            issueV(t + 1);  // overlaps QK^T(t+1)
            cp_commit();
        }
    }

    // ---- epilogue ----
#pragma unroll
    for (int mf = 0; mf < 2; mf++) {
        const float il0 = 1.f / lsum[mf][0], il1 = 1.f / lsum[mf][1];
        const int r0 = q0 + wrow + mf * 16 + g;
#pragma unroll
        for (int nf = 0; nf < 8; nf++) {
            const int c = h * D_H + nf * 8 + 2 * tg;
            *(float2*)(out + (size_t)(n * T_S + r0) * U_D + c) =
                make_float2(of[mf][nf][0] * il0, of[mf][nf][1] * il0);
            *(float2*)(out + (size_t)(n * T_S + r0 + 8) * U_D + c) =
                make_float2(of[mf][nf][2] * il1, of[mf][nf][3] * il1);
        }
    }
}

// ---------------------------------------------------------------------------
// Launch
// ---------------------------------------------------------------------------
extern "C" void kernel_launch(void* const* d_in, const int* in_sizes, int n_in,
                              void* d_out, int out_size) {
    const float* q = (const float*)d_in[0];
    const float* k = (const float*)d_in[1];
    const int* mask = (const int*)d_in[2];
    const float* Wq = (const float*)d_in[3];
    const float* Wk = (const float*)d_in[4];
    const float* Wv = (const float*)d_in[5];
    float* out = (float*)d_out;

    cudaFuncSetAttribute(proj_gemm, cudaFuncAttributeMaxDynamicSharedMemorySize, SM_GEMM);
    cudaFuncSetAttribute(attn_kernel, cudaFuncAttributeMaxDynamicSharedMemorySize, SM_ATTN);

    proj_gemm<<<dim3((N_B * T_S) / GBM, U_D / GBN, 3), 256, SM_GEMM>>>(q, k, Wq, Wk, Wv);

    // q-tiles x-fastest: 8 CTAs per (h,n) share the K/V slice in L2
    attn_kernel<<<dim3(T_S / QT, H_N, N_B), 128, SM_ATTN>>>(mask, out);
}

// round 8
// speedup vs baseline: 1.0799x; 1.0799x over previous
#include <cuda_runtime.h>
#include <cstdint>

#define N_B 8
#define T_S 1024
#define D_IN 512
#define U_D 512
#define H_N 8
#define D_H 64

// Scratch for projected Q, K, V: [N, T, U] fp32 (tf32-rounded; Q pre-scaled).
__device__ float g_Q[N_B * T_S * U_D];
__device__ float g_K[N_B * T_S * U_D];
__device__ float g_V[N_B * T_S * U_D];

// ---------------------------------------------------------------------------
// Helpers
// ---------------------------------------------------------------------------
__device__ __forceinline__ uint32_t f2tf32(float x) {
    uint32_t r;
    asm("cvt.rna.tf32.f32 %0, %1;" : "=r"(r) : "f"(x));
    return r;
}
__device__ __forceinline__ float f2tf32f(float x) { return __uint_as_float(f2tf32(x)); }

// D += A*B, m16n8k8 tf32. a[4], b[2] are tf32 bit patterns.
__device__ __forceinline__ void mma_tf32(float* d, const uint32_t* a, const uint32_t* b) {
    asm volatile(
        "mma.sync.aligned.m16n8k8.row.col.f32.tf32.tf32.f32 "
        "{%0,%1,%2,%3},{%4,%5,%6,%7},{%8,%9},{%0,%1,%2,%3};\n"
        : "+f"(d[0]), "+f"(d[1]), "+f"(d[2]), "+f"(d[3])
        : "r"(a[0]), "r"(a[1]), "r"(a[2]), "r"(a[3]), "r"(b[0]), "r"(b[1]));
}

__device__ __forceinline__ void ldsm4(uint32_t& r0, uint32_t& r1, uint32_t& r2, uint32_t& r3,
                                      uint32_t addr) {
    asm volatile("ldmatrix.sync.aligned.m8n8.x4.shared.b16 {%0,%1,%2,%3}, [%4];"
                 : "=r"(r0), "=r"(r1), "=r"(r2), "=r"(r3)
                 : "r"(addr));
}

// ---------------------------------------------------------------------------
// Projection GEMM: C[8192,512] = X[8192,512] @ W[512,512]
// Register-prefetch pipeline, cvt-at-STS, single smem buffer, B_LD=72.
// Epilogue rounds output to tf32 (Q additionally folded with 1/sqrt(512)) so
// the attention kernel consumes gmem directly without conversions.
// ---------------------------------------------------------------------------
#define GBM 128
#define GBN 64
#define GBK 32
#define A_LD 36
#define B_LD 72
#define SM_GEMM ((GBM * A_LD + GBK * B_LD) * 4)

__global__ void __launch_bounds__(256) proj_gemm(
    const float* __restrict__ Xq, const float* __restrict__ Xk,
    const float* __restrict__ Wq, const float* __restrict__ Wk,
    const float* __restrict__ Wv) {
    const float* X;
    const float* W;
    float* C;
    float oscale;
    if (blockIdx.z == 0) { X = Xq; W = Wq; C = g_Q; oscale = 0.04419417382415922f; }
    else if (blockIdx.z == 1) { X = Xk; W = Wk; C = g_K; oscale = 1.0f; }
    else { X = Xk; W = Wv; C = g_V; oscale = 1.0f; }

    extern __shared__ float sm[];
    float* As = sm;                 // [GBM][A_LD]
    float* Bs = sm + GBM * A_LD;    // [GBK][B_LD]

    const int tid = threadIdx.x;
    const int m0 = blockIdx.x * GBM, n0 = blockIdx.y * GBN;
    const int ar = tid >> 3, ac = (tid & 7) * 4;
    const int br = tid >> 4, bc = (tid & 15) * 4;

    const int lane = tid & 31, wid = tid >> 5;
    const int g = lane >> 2, tg = lane & 3;
    const int wm = (wid & 3) * 32, wn = (wid >> 2) * 32;

    float acc[2][4][4];
#pragma unroll
    for (int mf = 0; mf < 2; mf++)
#pragma unroll
        for (int nf = 0; nf < 4; nf++)
#pragma unroll
            for (int i = 0; i < 4; i++) acc[mf][nf][i] = 0.f;

    const int NK = D_IN / GBK;  // 16

    float4 pa[4], pb[2];
    auto ldreg = [&](int kt) {
#pragma unroll
        for (int i = 0; i < 4; i++)
            pa[i] = *(const float4*)(X + (size_t)(m0 + ar + i * 32) * D_IN + kt * GBK + ac);
#pragma unroll
        for (int i = 0; i < 2; i++)
            pb[i] = *(const float4*)(W + (size_t)(kt * GBK + br + i * 16) * U_D + n0 + bc);
    };

    ldreg(0);

    for (int kt = 0; kt < NK; ++kt) {
        __syncthreads();
#pragma unroll
        for (int i = 0; i < 4; i++) {
            float4 o;
            o.x = f2tf32f(pa[i].x); o.y = f2tf32f(pa[i].y);
            o.z = f2tf32f(pa[i].z); o.w = f2tf32f(pa[i].w);
            *(float4*)(As + (ar + i * 32) * A_LD + ac) = o;
        }
#pragma unroll
        for (int i = 0; i < 2; i++) {
            float4 o;
            o.x = f2tf32f(pb[i].x); o.y = f2tf32f(pb[i].y);
            o.z = f2tf32f(pb[i].z); o.w = f2tf32f(pb[i].w);
            *(float4*)(Bs + (br + i * 16) * B_LD + bc) = o;
        }
        __syncthreads();

        if (kt + 1 < NK) ldreg(kt + 1);

#pragma unroll
        for (int kk = 0; kk < 4; kk++) {
            uint32_t a[2][4];
#pragma unroll
            for (int mf = 0; mf < 2; mf++) {
                const int rb = wm + mf * 16;
                a[mf][0] = __float_as_uint(As[(rb + g) * A_LD + kk * 8 + tg]);
                a[mf][1] = __float_as_uint(As[(rb + g + 8) * A_LD + kk * 8 + tg]);
                a[mf][2] = __float_as_uint(As[(rb + g) * A_LD + kk * 8 + tg + 4]);
                a[mf][3] = __float_as_uint(As[(rb + g + 8) * A_LD + kk * 8 + tg + 4]);
            }
            uint32_t b[4][2];
#pragma unroll
            for (int nf = 0; nf < 4; nf++) {
                b[nf][0] = __float_as_uint(Bs[(kk * 8 + tg) * B_LD + wn + nf * 8 + g]);
                b[nf][1] = __float_as_uint(Bs[(kk * 8 + tg + 4) * B_LD + wn + nf * 8 + g]);
            }
#pragma unroll
            for (int mf = 0; mf < 2; mf++)
#pragma unroll
                for (int nf = 0; nf < 4; nf++) mma_tf32(acc[mf][nf], a[mf], b[nf]);
        }
    }

    // epilogue: tf32-round (fold scale for Q) so attn consumes gmem directly
#pragma unroll
    for (int mf = 0; mf < 2; mf++) {
        const int r0 = m0 + wm + mf * 16 + g;
#pragma unroll
        for (int nf = 0; nf < 4; nf++) {
            const int c = n0 + wn + nf * 8 + 2 * tg;
            *(float2*)(C + (size_t)r0 * U_D + c) =
                make_float2(f2tf32f(acc[mf][nf][0] * oscale), f2tf32f(acc[mf][nf][1] * oscale));
            *(float2*)(C + (size_t)(r0 + 8) * U_D + c) =
                make_float2(f2tf32f(acc[mf][nf][2] * oscale), f2tf32f(acc[mf][nf][3] * oscale));
        }
    }
}

// ---------------------------------------------------------------------------
// Flash attention v6 (best R6 config + Q fragments hoisted to registers):
// - Q loaded to smem once, ldsm'd into 64 regs in the prologue, smem region
//   then reused for Ps (aliased) -> 70.9 KB smem.
// - Mainloop: synchronous K/V float4 copies (gmem pre-rounded tf32, no cvt),
//   KT=64, 2 barriers/iter; QK^T A-operands come straight from registers.
// CTA = 128 q-rows x 4 warps; warp owns 32 rows (2 m-frags).
// ---------------------------------------------------------------------------
#define QT 128
#define KT 64
#define AL 68     // LD for Q(prologue)/Ks/Ps
#define VL 72     // LD for Vs (8*tg+g hits all 32 banks)
#define SM_ATTN ((QT * AL + KT * AL + KT * VL + KT) * 4)

__global__ void __launch_bounds__(128) attn_kernel(const int* __restrict__ mask,
                                                   float* __restrict__ out) {
    extern __shared__ float sm[];
    float* Ps = sm;                       // [128][AL]; prologue: holds Q tile
    float* Ks = Ps + QT * AL;             // [64][AL]  tf32
    float* Vs = Ks + KT * AL;             // [64][VL]  tf32
    float* Msk = Vs + KT * VL;            // [64] 1.0 = masked-out

    const int tid = threadIdx.x, lane = tid & 31, wid = tid >> 5;
    const int g = lane >> 2, tg = lane & 3;
    const int q0 = blockIdx.x * QT;
    const int h = blockIdx.y, n = blockIdx.z;
    const int wrow = wid * 32;

    const uint32_t sP = (uint32_t)__cvta_generic_to_shared(Ps);
    const uint32_t sK = (uint32_t)__cvta_generic_to_shared(Ks);

    // ldmatrix per-lane offsets (floats)
    const int li = lane & 7, lj = lane >> 3;
    const int aoff = (li + (lj & 1) * 8) * AL + (lj >> 1) * 4;  // 16x8 A-frag
    const int boff = (li + (lj >> 1) * 8) * AL + (lj & 1) * 4;  // 2x(8k x 8c) B

    const int lr = tid >> 4;   // 0..7
    const int fc = tid & 15;   // float4 column

    // ---- Q prologue: copy tile into smem (pre-scaled tf32), ldsm to regs ----
#pragma unroll
    for (int i = 0; i < 16; i++) {
        const int r = lr + i * 8;
        *(float4*)(Ps + r * AL + fc * 4) =
            *(const float4*)(g_Q + (size_t)(n * T_S + q0 + r) * U_D + h * D_H + fc * 4);
    }
    __syncthreads();

    uint32_t qa[8][2][4];  // [kk][mf][reg] -- Q resident in registers
#pragma unroll
    for (int kk = 0; kk < 8; kk++) {
        ldsm4(qa[kk][0][0], qa[kk][0][1], qa[kk][0][2], qa[kk][0][3],
              sP + 4u * (uint32_t)(wrow * AL + kk * 8 + aoff));
        ldsm4(qa[kk][1][0], qa[kk][1][1], qa[kk][1][2], qa[kk][1][3],
              sP + 4u * (uint32_t)((wrow + 16) * AL + kk * 8 + aoff));
    }
    // Ps region is now free for P tiles (first write happens after the
    // loop's first __syncthreads, so no race with other warps' ldsm).

    float mr[2][2], lsum[2][2];
#pragma unroll
    for (int mf = 0; mf < 2; mf++) { mr[mf][0] = mr[mf][1] = -1e30f; lsum[mf][0] = lsum[mf][1] = 0.f; }
    float of[2][8][4];
#pragma unroll
    for (int mf = 0; mf < 2; mf++)
#pragma unroll
        for (int nf = 0; nf < 8; nf++)
#pragma unroll
            for (int i = 0; i < 4; i++) of[mf][nf][i] = 0.f;

    for (int kt = 0; kt < 16; kt++) {
        __syncthreads();  // prior-tile consumers done (and Q ldsm on kt=0)
        const int j0 = kt * KT;
#pragma unroll
        for (int i = 0; i < 8; i++) {
            const int r = lr + i * 8;
            const size_t gb = (size_t)(n * T_S + j0 + r) * U_D + h * D_H + fc * 4;
            *(float4*)(Ks + r * AL + fc * 4) = *(const float4*)(g_K + gb);
            *(float4*)(Vs + r * VL + fc * 4) = *(const float4*)(g_V + gb);
        }
        if (tid < KT) Msk[tid] = (mask[n * T_S + j0 + tid] != 0) ? 0.f : 1.f;
        __syncthreads();

        // ---- S = Q @ K^T (A from registers) ----
        float sf[2][8][4];
#pragma unroll
        for (int mf = 0; mf < 2; mf++)
#pragma unroll
            for (int nf = 0; nf < 8; nf++)
#pragma unroll
                for (int i = 0; i < 4; i++) sf[mf][nf][i] = 0.f;

#pragma unroll
        for (int kk = 0; kk < 8; kk++) {
#pragma unroll
            for (int nfp = 0; nfp < 4; nfp++) {
                uint32_t kb[4];
                ldsm4(kb[0], kb[1], kb[2], kb[3],
                      sK + 4u * (uint32_t)(nfp * 16 * AL + kk * 8 + boff));
                mma_tf32(sf[0][2 * nfp], qa[kk][0], kb);
                mma_tf32(sf[1][2 * nfp], qa[kk][1], kb);
                mma_tf32(sf[0][2 * nfp + 1], qa[kk][0], kb + 2);
                mma_tf32(sf[1][2 * nfp + 1], qa[kk][1], kb + 2);
            }
        }

        // ---- mask (jnp.where(mask, s, -1e6)) ----
#pragma unroll
        for (int nf = 0; nf < 8; nf++) {
            const float f0 = Msk[nf * 8 + 2 * tg];
            const float f1 = Msk[nf * 8 + 2 * tg + 1];
#pragma unroll
            for (int mf = 0; mf < 2; mf++) {
                if (f0 != 0.f) { sf[mf][nf][0] = -1e6f; sf[mf][nf][2] = -1e6f; }
                if (f1 != 0.f) { sf[mf][nf][1] = -1e6f; sf[mf][nf][3] = -1e6f; }
            }
        }

        // ---- online softmax + P store ----
#pragma unroll
        for (int mf = 0; mf < 2; mf++) {
            float rm0 = -1e30f, rm1 = -1e30f;
#pragma unroll
            for (int nf = 0; nf < 8; nf++) {
                rm0 = fmaxf(rm0, fmaxf(sf[mf][nf][0], sf[mf][nf][1]));
                rm1 = fmaxf(rm1, fmaxf(sf[mf][nf][2], sf[mf][nf][3]));
            }
            rm0 = fmaxf(rm0, __shfl_xor_sync(0xffffffffu, rm0, 1));
            rm0 = fmaxf(rm0, __shfl_xor_sync(0xffffffffu, rm0, 2));
            rm1 = fmaxf(rm1, __shfl_xor_sync(0xffffffffu, rm1, 1));
            rm1 = fmaxf(rm1, __shfl_xor_sync(0xffffffffu, rm1, 2));

            const float mn0 = fmaxf(mr[mf][0], rm0), mn1 = fmaxf(mr[mf][1], rm1);
            const float al0 = __expf(mr[mf][0] - mn0), al1 = __expf(mr[mf][1] - mn1);
            float rs0 = 0.f, rs1 = 0.f;
#pragma unroll
            for (int nf = 0; nf < 8; nf++) {
                sf[mf][nf][0] = __expf(sf[mf][nf][0] - mn0);
                sf[mf][nf][1] = __expf(sf[mf][nf][1] - mn0);
                sf[mf][nf][2] = __expf(sf[mf][nf][2] - mn1);
                sf[mf][nf][3] = __expf(sf[mf][nf][3] - mn1);
                rs0 += sf[mf][nf][0] + sf[mf][nf][1];
                rs1 += sf[mf][nf][2] + sf[mf][nf][3];
            }
            rs0 += __shfl_xor_sync(0xffffffffu, rs0, 1);
            rs0 += __shfl_xor_sync(0xffffffffu, rs0, 2);
            rs1 += __shfl_xor_sync(0xffffffffu, rs1, 1);
            rs1 += __shfl_xor_sync(0xffffffffu, rs1, 2);

            lsum[mf][0] = lsum[mf][0] * al0 + rs0;
            lsum[mf][1] = lsum[mf][1] * al1 + rs1;
            mr[mf][0] = mn0;
            mr[mf][1] = mn1;

#pragma unroll
            for (int nf = 0; nf < 8; nf++) {
                of[mf][nf][0] *= al0;
                of[mf][nf][1] *= al0;
                of[mf][nf][2] *= al1;
                of[mf][nf][3] *= al1;
            }

            const int pr = wrow + mf * 16;
#pragma unroll
            for (int nf = 0; nf < 8; nf++) {
                *(float2*)(Ps + (pr + g) * AL + nf * 8 + 2 * tg) =
                    make_float2(f2tf32f(sf[mf][nf][0]), f2tf32f(sf[mf][nf][1]));
                *(float2*)(Ps + (pr + g + 8) * AL + nf * 8 + 2 * tg) =
                    make_float2(f2tf32f(sf[mf][nf][2]), f2tf32f(sf[mf][nf][3]));
            }
        }
        __syncwarp();

        // ---- O += P @ V ----
#pragma unroll
        for (int kks = 0; kks < 8; kks++) {
            uint32_t pa[2][4];
            ldsm4(pa[0][0], pa[0][1], pa[0][2], pa[0][3],
                  sP + 4u * (uint32_t)(wrow * AL + kks * 8 + aoff));
            ldsm4(pa[1][0], pa[1][1], pa[1][2], pa[1][3],
                  sP + 4u * (uint32_t)((wrow + 16) * AL + kks * 8 + aoff));
#pragma unroll
            for (int nf = 0; nf < 8; nf++) {
                uint32_t vb[2];
                vb[0] = __float_as_uint(Vs[(kks * 8 + tg) * VL + nf * 8 + g]);
                vb[1] = __float_as_uint(Vs[(kks * 8 + tg + 4) * VL + nf * 8 + g]);
                mma_tf32(of[0][nf], pa[0], vb);
                mma_tf32(of[1][nf], pa[1], vb);
            }
        }
    }

    // ---- epilogue ----
#pragma unroll
    for (int mf = 0; mf < 2; mf++) {
        const float il0 = 1.f / lsum[mf][0], il1 = 1.f / lsum[mf][1];
        const int r0 = q0 + wrow + mf * 16 + g;
#pragma unroll
        for (int nf = 0; nf < 8; nf++) {
            const int c = h * D_H + nf * 8 + 2 * tg;
            *(float2*)(out + (size_t)(n * T_S + r0) * U_D + c) =
                make_float2(of[mf][nf][0] * il0, of[mf][nf][1] * il0);
            *(float2*)(out + (size_t)(n * T_S + r0 + 8) * U_D + c) =
                make_float2(of[mf][nf][2] * il1, of[mf][nf][3] * il1);
        }
    }
}

// ---------------------------------------------------------------------------
// Launch
// ---------------------------------------------------------------------------
extern "C" void kernel_launch(void* const* d_in, const int* in_sizes, int n_in,
                              void* d_out, int out_size) {
    const float* q = (const float*)d_in[0];
    const float* k = (const float*)d_in[1];
    const int* mask = (const int*)d_in[2];
    const float* Wq = (const float*)d_in[3];
    const float* Wk = (const float*)d_in[4];
    const float* Wv = (const float*)d_in[5];
    float* out = (float*)d_out;

    cudaFuncSetAttribute(proj_gemm, cudaFuncAttributeMaxDynamicSharedMemorySize, SM_GEMM);
    cudaFuncSetAttribute(attn_kernel, cudaFuncAttributeMaxDynamicSharedMemorySize, SM_ATTN);

    proj_gemm<<<dim3((N_B * T_S) / GBM, U_D / GBN, 3), 256, SM_GEMM>>>(q, k, Wq, Wk, Wv);

    // q-tiles x-fastest: 8 CTAs per (h,n) share the K/V slice in L2
    attn_kernel<<<dim3(T_S / QT, H_N, N_B), 128, SM_ATTN>>>(mask, out);
}

// round 9
// speedup vs baseline: 1.2378x; 1.1462x over previous
#include <cuda_runtime.h>
#include <cstdint>

#define N_B 8
#define T_S 1024
#define D_IN 512
#define U_D 512
#define H_N 8
#define D_H 64

// Scratch for projected Q, K, V: [N, T, U] fp32 (tf32-rounded; Q pre-scaled).
__device__ float g_Q[N_B * T_S * U_D];
__device__ float g_K[N_B * T_S * U_D];
__device__ float g_V[N_B * T_S * U_D];

// ---------------------------------------------------------------------------
// Helpers
// ---------------------------------------------------------------------------
__device__ __forceinline__ uint32_t f2tf32(float x) {
    uint32_t r;
    asm("cvt.rna.tf32.f32 %0, %1;" : "=r"(r) : "f"(x));
    return r;
}
__device__ __forceinline__ float f2tf32f(float x) { return __uint_as_float(f2tf32(x)); }

// D += A*B, m16n8k8 tf32. a[4], b[2] are tf32 bit patterns.
__device__ __forceinline__ void mma_tf32(float* d, const uint32_t* a, const uint32_t* b) {
    asm volatile(
        "mma.sync.aligned.m16n8k8.row.col.f32.tf32.tf32.f32 "
        "{%0,%1,%2,%3},{%4,%5,%6,%7},{%8,%9},{%0,%1,%2,%3};\n"
        : "+f"(d[0]), "+f"(d[1]), "+f"(d[2]), "+f"(d[3])
        : "r"(a[0]), "r"(a[1]), "r"(a[2]), "r"(a[3]), "r"(b[0]), "r"(b[1]));
}

__device__ __forceinline__ void ldsm4(uint32_t& r0, uint32_t& r1, uint32_t& r2, uint32_t& r3,
                                      uint32_t addr) {
    asm volatile("ldmatrix.sync.aligned.m8n8.x4.shared.b16 {%0,%1,%2,%3}, [%4];"
                 : "=r"(r0), "=r"(r1), "=r"(r2), "=r"(r3)
                 : "r"(addr));
}

// ---------------------------------------------------------------------------
// Projection GEMM v3: C[8192,512] = X[8192,512] @ W[512,512]
// BM=128, BN=128, BK=32; 256 threads, warp tile 32x64 (2 m-frags x 8 n-frags).
// A-fragments via ldmatrix, B scalar conflict-free (B_LD=136 -> 8*tg+g banks).
// Register prefetch pipeline, cvt-at-STS. Epilogue rounds output to tf32
// (Q folded with 1/sqrt(512)) so attn consumes gmem directly, no cvts.
// ---------------------------------------------------------------------------
#define GBM 128
#define GBN 128
#define GBK 32
#define A_LD 36
#define B_LD 136
#define SM_GEMM ((GBM * A_LD + GBK * B_LD) * 4)

__global__ void __launch_bounds__(256) proj_gemm(
    const float* __restrict__ Xq, const float* __restrict__ Xk,
    const float* __restrict__ Wq, const float* __restrict__ Wk,
    const float* __restrict__ Wv) {
    const float* X;
    const float* W;
    float* C;
    float oscale;
    if (blockIdx.z == 0) { X = Xq; W = Wq; C = g_Q; oscale = 0.04419417382415922f; }
    else if (blockIdx.z == 1) { X = Xk; W = Wk; C = g_K; oscale = 1.0f; }
    else { X = Xk; W = Wv; C = g_V; oscale = 1.0f; }

    extern __shared__ float sm[];
    float* As = sm;                 // [GBM][A_LD]  (m-major for ldsm A-frags)
    float* Bs = sm + GBM * A_LD;    // [GBK][B_LD]  (k-major, scalar B-frags)

    const int tid = threadIdx.x;
    const int m0 = blockIdx.x * GBM, n0 = blockIdx.y * GBN;
    const int ar = tid >> 3, ac = (tid & 7) * 4;     // A: 32 rows/step, 8 f4/row
    const int br = tid >> 5, bc = (tid & 31) * 4;    // B: 8 rows/step, 32 f4/row

    const int lane = tid & 31, wid = tid >> 5;
    const int g = lane >> 2, tg = lane & 3;
    const int wm = (wid & 3) * 32, wn = (wid >> 2) * 64;

    // ldmatrix A-frag per-lane offset (16x8 pattern, floats)
    const int li = lane & 7, lj = lane >> 3;
    const int aoff = (li + (lj & 1) * 8) * A_LD + (lj >> 1) * 4;
    const uint32_t sA = (uint32_t)__cvta_generic_to_shared(As);

    float acc[2][8][4];
#pragma unroll
    for (int mf = 0; mf < 2; mf++)
#pragma unroll
        for (int nf = 0; nf < 8; nf++)
#pragma unroll
            for (int i = 0; i < 4; i++) acc[mf][nf][i] = 0.f;

    const int NK = D_IN / GBK;  // 16

    float4 pa[4], pb[4];
    auto ldreg = [&](int kt) {
#pragma unroll
        for (int i = 0; i < 4; i++)
            pa[i] = *(const float4*)(X + (size_t)(m0 + ar + i * 32) * D_IN + kt * GBK + ac);
#pragma unroll
        for (int i = 0; i < 4; i++)
            pb[i] = *(const float4*)(W + (size_t)(kt * GBK + br + i * 8) * U_D + n0 + bc);
    };

    ldreg(0);

    for (int kt = 0; kt < NK; ++kt) {
        __syncthreads();
#pragma unroll
        for (int i = 0; i < 4; i++) {
            float4 o;
            o.x = f2tf32f(pa[i].x); o.y = f2tf32f(pa[i].y);
            o.z = f2tf32f(pa[i].z); o.w = f2tf32f(pa[i].w);
            *(float4*)(As + (ar + i * 32) * A_LD + ac) = o;
        }
#pragma unroll
        for (int i = 0; i < 4; i++) {
            float4 o;
            o.x = f2tf32f(pb[i].x); o.y = f2tf32f(pb[i].y);
            o.z = f2tf32f(pb[i].z); o.w = f2tf32f(pb[i].w);
            *(float4*)(Bs + (br + i * 8) * B_LD + bc) = o;
        }
        __syncthreads();

        if (kt + 1 < NK) ldreg(kt + 1);

#pragma unroll
        for (int kk = 0; kk < 4; kk++) {
            uint32_t a[2][4];
            ldsm4(a[0][0], a[0][1], a[0][2], a[0][3],
                  sA + 4u * (uint32_t)(wm * A_LD + kk * 8 + aoff));
            ldsm4(a[1][0], a[1][1], a[1][2], a[1][3],
                  sA + 4u * (uint32_t)((wm + 16) * A_LD + kk * 8 + aoff));
#pragma unroll
            for (int nf = 0; nf < 8; nf++) {
                uint32_t b[2];
                b[0] = __float_as_uint(Bs[(kk * 8 + tg) * B_LD + wn + nf * 8 + g]);
                b[1] = __float_as_uint(Bs[(kk * 8 + tg + 4) * B_LD + wn + nf * 8 + g]);
                mma_tf32(acc[0][nf], a[0], b);
                mma_tf32(acc[1][nf], a[1], b);
            }
        }
    }

    // epilogue: tf32-round (fold scale for Q) so attn consumes gmem directly
#pragma unroll
    for (int mf = 0; mf < 2; mf++) {
        const int r0 = m0 + wm + mf * 16 + g;
#pragma unroll
        for (int nf = 0; nf < 8; nf++) {
            const int c = n0 + wn + nf * 8 + 2 * tg;
            *(float2*)(C + (size_t)r0 * U_D + c) =
                make_float2(f2tf32f(acc[mf][nf][0] * oscale), f2tf32f(acc[mf][nf][1] * oscale));
            *(float2*)(C + (size_t)(r0 + 8) * U_D + c) =
                make_float2(f2tf32f(acc[mf][nf][2] * oscale), f2tf32f(acc[mf][nf][3] * oscale));
        }
    }
}

// ---------------------------------------------------------------------------
// Flash attention (R6 best-measured config, byte-identical):
// KT=64, synchronous K/V float4 copies (gmem pre-rounded tf32, no cvt),
// Q/K/P fragments via ldmatrix, V scalar conflict-free (VL=72), 2 barriers
// per tile. CTA = 128 q-rows x 4 warps; warp owns 32 rows (2 m-frags).
// ---------------------------------------------------------------------------
#define QT 128
#define KT 64
#define AL 68     // LD for Qs/Ks/Ps
#define VL 72     // LD for Vs (8*tg+g hits all 32 banks)
#define SM_ATTN ((QT * AL + KT * AL + KT * VL + QT * AL + KT) * 4)

__global__ void __launch_bounds__(128) attn_kernel(const int* __restrict__ mask,
                                                   float* __restrict__ out) {
    extern __shared__ float sm[];
    float* Qs = sm;                       // [128][AL] tf32, scale folded
    float* Ks = Qs + QT * AL;             // [64][AL]  tf32
    float* Vs = Ks + KT * AL;             // [64][VL]  tf32
    float* Ps = Vs + KT * VL;             // [128][AL] tf32
    float* Msk = Ps + QT * AL;            // [64] 1.0 = masked-out

    const int tid = threadIdx.x, lane = tid & 31, wid = tid >> 5;
    const int g = lane >> 2, tg = lane & 3;
    const int q0 = blockIdx.x * QT;
    const int h = blockIdx.y, n = blockIdx.z;
    const int wrow = wid * 32;

    const uint32_t sQ = (uint32_t)__cvta_generic_to_shared(Qs);
    const uint32_t sK = (uint32_t)__cvta_generic_to_shared(Ks);
    const uint32_t sP = (uint32_t)__cvta_generic_to_shared(Ps);

    // ldmatrix per-lane offsets (floats)
    const int li = lane & 7, lj = lane >> 3;
    const int aoff = (li + (lj & 1) * 8) * AL + (lj >> 1) * 4;  // 16x8 A-frag
    const int boff = (li + (lj >> 1) * 8) * AL + (lj & 1) * 4;  // 2x(8k x 8c) B

    const int lr = tid >> 4;   // 0..7
    const int fc = tid & 15;   // float4 column

    // ---- Q prologue: straight copy (already tf32-rounded + scaled) ----
#pragma unroll
    for (int i = 0; i < 16; i++) {
        const int r = lr + i * 8;
        *(float4*)(Qs + r * AL + fc * 4) =
            *(const float4*)(g_Q + (size_t)(n * T_S + q0 + r) * U_D + h * D_H + fc * 4);
    }

    float mr[2][2], lsum[2][2];
#pragma unroll
    for (int mf = 0; mf < 2; mf++) { mr[mf][0] = mr[mf][1] = -1e30f; lsum[mf][0] = lsum[mf][1] = 0.f; }
    float of[2][8][4];
#pragma unroll
    for (int mf = 0; mf < 2; mf++)
#pragma unroll
        for (int nf = 0; nf < 8; nf++)
#pragma unroll
            for (int i = 0; i < 4; i++) of[mf][nf][i] = 0.f;

    for (int kt = 0; kt < 16; kt++) {
        __syncthreads();  // prior-tile consumers done (and Q store on kt=0)
        const int j0 = kt * KT;
#pragma unroll
        for (int i = 0; i < 8; i++) {
            const int r = lr + i * 8;
            const size_t gb = (size_t)(n * T_S + j0 + r) * U_D + h * D_H + fc * 4;
            *(float4*)(Ks + r * AL + fc * 4) = *(const float4*)(g_K + gb);
            *(float4*)(Vs + r * VL + fc * 4) = *(const float4*)(g_V + gb);
        }
        if (tid < KT) Msk[tid] = (mask[n * T_S + j0 + tid] != 0) ? 0.f : 1.f;
        __syncthreads();

        // ---- S = Q @ K^T ----
        float sf[2][8][4];
#pragma unroll
        for (int mf = 0; mf < 2; mf++)
#pragma unroll
            for (int nf = 0; nf < 8; nf++)
#pragma unroll
                for (int i = 0; i < 4; i++) sf[mf][nf][i] = 0.f;

#pragma unroll
        for (int kk = 0; kk < 8; kk++) {
            uint32_t qa[2][4];
            ldsm4(qa[0][0], qa[0][1], qa[0][2], qa[0][3],
                  sQ + 4u * (uint32_t)(wrow * AL + kk * 8 + aoff));
            ldsm4(qa[1][0], qa[1][1], qa[1][2], qa[1][3],
                  sQ + 4u * (uint32_t)((wrow + 16) * AL + kk * 8 + aoff));
#pragma unroll
            for (int nfp = 0; nfp < 4; nfp++) {
                uint32_t kb[4];
                ldsm4(kb[0], kb[1], kb[2], kb[3],
                      sK + 4u * (uint32_t)(nfp * 16 * AL + kk * 8 + boff));
                mma_tf32(sf[0][2 * nfp], qa[0], kb);
                mma_tf32(sf[1][2 * nfp], qa[1], kb);
                mma_tf32(sf[0][2 * nfp + 1], qa[0], kb + 2);
                mma_tf32(sf[1][2 * nfp + 1], qa[1], kb + 2);
            }
        }

        // ---- mask (jnp.where(mask, s, -1e6)) ----
#pragma unroll
        for (int nf = 0; nf < 8; nf++) {
            const float f0 = Msk[nf * 8 + 2 * tg];
            const float f1 = Msk[nf * 8 + 2 * tg + 1];
#pragma unroll
            for (int mf = 0; mf < 2; mf++) {
                if (f0 != 0.f) { sf[mf][nf][0] = -1e6f; sf[mf][nf][2] = -1e6f; }
                if (f1 != 0.f) { sf[mf][nf][1] = -1e6f; sf[mf][nf][3] = -1e6f; }
            }
        }

        // ---- online softmax + P store ----
#pragma unroll
        for (int mf = 0; mf < 2; mf++) {
            float rm0 = -1e30f, rm1 = -1e30f;
#pragma unroll
            for (int nf = 0; nf < 8; nf++) {
                rm0 = fmaxf(rm0, fmaxf(sf[mf][nf][0], sf[mf][nf][1]));
                rm1 = fmaxf(rm1, fmaxf(sf[mf][nf][2], sf[mf][nf][3]));
            }
            rm0 = fmaxf(rm0, __shfl_xor_sync(0xffffffffu, rm0, 1));
            rm0 = fmaxf(rm0, __shfl_xor_sync(0xffffffffu, rm0, 2));
            rm1 = fmaxf(rm1, __shfl_xor_sync(0xffffffffu, rm1, 1));
            rm1 = fmaxf(rm1, __shfl_xor_sync(0xffffffffu, rm1, 2));

            const float mn0 = fmaxf(mr[mf][0], rm0), mn1 = fmaxf(mr[mf][1], rm1);
            const float al0 = __expf(mr[mf][0] - mn0), al1 = __expf(mr[mf][1] - mn1);
            float rs0 = 0.f, rs1 = 0.f;
#pragma unroll
            for (int nf = 0; nf < 8; nf++) {
                sf[mf][nf][0] = __expf(sf[mf][nf][0] - mn0);
                sf[mf][nf][1] = __expf(sf[mf][nf][1] - mn0);
                sf[mf][nf][2] = __expf(sf[mf][nf][2] - mn1);
                sf[mf][nf][3] = __expf(sf[mf][nf][3] - mn1);
                rs0 += sf[mf][nf][0] + sf[mf][nf][1];
                rs1 += sf[mf][nf][2] + sf[mf][nf][3];
            }
            rs0 += __shfl_xor_sync(0xffffffffu, rs0, 1);
            rs0 += __shfl_xor_sync(0xffffffffu, rs0, 2);
            rs1 += __shfl_xor_sync(0xffffffffu, rs1, 1);
            rs1 += __shfl_xor_sync(0xffffffffu, rs1, 2);

            lsum[mf][0] = lsum[mf][0] * al0 + rs0;
            lsum[mf][1] = lsum[mf][1] * al1 + rs1;
            mr[mf][0] = mn0;
            mr[mf][1] = mn1;

#pragma unroll
            for (int nf = 0; nf < 8; nf++) {
                of[mf][nf][0] *= al0;
                of[mf][nf][1] *= al0;
                of[mf][nf][2] *= al1;
                of[mf][nf][3] *= al1;
            }

            const int pr = wrow + mf * 16;
#pragma unroll
            for (int nf = 0; nf < 8; nf++) {
                *(float2*)(Ps + (pr + g) * AL + nf * 8 + 2 * tg) =
                    make_float2(f2tf32f(sf[mf][nf][0]), f2tf32f(sf[mf][nf][1]));
                *(float2*)(Ps + (pr + g + 8) * AL + nf * 8 + 2 * tg) =
                    make_float2(f2tf32f(sf[mf][nf][2]), f2tf32f(sf[mf][nf][3]));
            }
        }
        __syncwarp();

        // ---- O += P @ V ----
#pragma unroll
        for (int kks = 0; kks < 8; kks++) {
            uint32_t pa[2][4];
            ldsm4(pa[0][0], pa[0][1], pa[0][2], pa[0][3],
                  sP + 4u * (uint32_t)(wrow * AL + kks * 8 + aoff));
            ldsm4(pa[1][0], pa[1][1], pa[1][2], pa[1][3],
                  sP + 4u * (uint32_t)((wrow + 16) * AL + kks * 8 + aoff));
#pragma unroll
            for (int nf = 0; nf < 8; nf++) {
                uint32_t vb[2];
                vb[0] = __float_as_uint(Vs[(kks * 8 + tg) * VL + nf * 8 + g]);
                vb[1] = __float_as_uint(Vs[(kks * 8 + tg + 4) * VL + nf * 8 + g]);
                mma_tf32(of[0][nf], pa[0], vb);
                mma_tf32(of[1][nf], pa[1], vb);
            }
        }
    }

    // ---- epilogue ----
#pragma unroll
    for (int mf = 0; mf < 2; mf++) {
        const float il0 = 1.f / lsum[mf][0], il1 = 1.f / lsum[mf][1];
        const int r0 = q0 + wrow + mf * 16 + g;
#pragma unroll
        for (int nf = 0; nf < 8; nf++) {
            const int c = h * D_H + nf * 8 + 2 * tg;
            *(float2*)(out + (size_t)(n * T_S + r0) * U_D + c) =
                make_float2(of[mf][nf][0] * il0, of[mf][nf][1] * il0);
            *(float2*)(out + (size_t)(n * T_S + r0 + 8) * U_D + c) =
                make_float2(of[mf][nf][2] * il1, of[mf][nf][3] * il1);
        }
    }
}

// ---------------------------------------------------------------------------
// Launch
// ---------------------------------------------------------------------------
extern "C" void kernel_launch(void* const* d_in, const int* in_sizes, int n_in,
                              void* d_out, int out_size) {
    const float* q = (const float*)d_in[0];
    const float* k = (const float*)d_in[1];
    const int* mask = (const int*)d_in[2];
    const float* Wq = (const float*)d_in[3];
    const float* Wk = (const float*)d_in[4];
    const float* Wv = (const float*)d_in[5];
    float* out = (float*)d_out;

    cudaFuncSetAttribute(proj_gemm, cudaFuncAttributeMaxDynamicSharedMemorySize, SM_GEMM);
    cudaFuncSetAttribute(attn_kernel, cudaFuncAttributeMaxDynamicSharedMemorySize, SM_ATTN);

    // Projections: 64 x 4 x 3 = 768 CTAs of 256 threads
    proj_gemm<<<dim3((N_B * T_S) / GBM, U_D / GBN, 3), 256, SM_GEMM>>>(q, k, Wq, Wk, Wv);

    // q-tiles x-fastest: 8 CTAs per (h,n) share the K/V slice in L2
    attn_kernel<<<dim3(T_S / QT, H_N, N_B), 128, SM_ATTN>>>(mask, out);
}